// round 10
// baseline (speedup 1.0000x reference)
#include <cuda_runtime.h>
#include <cuda_bf16.h>

#define VOCAB 32000
#define EMB   256
#define HID   512
#define BATCH 64
#define SEQ   512

typedef unsigned long long ull;

// ------------------------- device scratch (no runtime alloc) ---------------
__device__ float g_xin[(size_t)SEQ * BATCH * HID];     // [s][b][i]
__device__ float g_states[(size_t)SEQ * BATCH * HID];  // [s][b][i]
__device__ float g_feat[BATCH * 2 * HID];              // [b][1024]

// ------------------------- packed fp32x2 helpers ---------------------------
__device__ __forceinline__ void fma2(ull& d, ull a, ull b) {
    asm("fma.rn.f32x2 %0, %1, %2, %0;" : "+l"(d) : "l"(a), "l"(b));
}
__device__ __forceinline__ float2 unpack2(ull v) {
    float lo, hi;
    asm("mov.b64 {%0, %1}, %2;" : "=f"(lo), "=f"(hi) : "l"(v));
    return make_float2(lo, hi);
}
__device__ __forceinline__ ull dup2(float x) {
    ull r;
    asm("mov.b64 %0, {%1, %1};" : "=l"(r) : "f"(x));
    return r;
}
__device__ __forceinline__ unsigned smem_u32(const void* p) {
    unsigned a;
    asm("{ .reg .u64 t; cvta.to.shared.u64 t, %1; cvt.u32.u64 %0, t; }"
        : "=r"(a) : "l"(p));
    return a;
}
// fast tanh: 1 - 2/(exp(2x)+1).  MUFU-based, abs err ~1e-7, saturates right.
__device__ __forceinline__ float ftanh(float x) {
    float e = __expf(2.f * x);
    return 1.f - __fdividef(2.f, e + 1.f);
}

// ------------------------- mbarrier primitives -----------------------------
__device__ __forceinline__ void mbar_init(unsigned mbar, unsigned cnt) {
    asm volatile("mbarrier.init.shared.b64 [%0], %1;" :: "r"(mbar), "r"(cnt) : "memory");
}
__device__ __forceinline__ void mbar_arrive_remote(unsigned mbar) {
    asm volatile("mbarrier.arrive.release.cluster.shared::cluster.b64 _, [%0];"
                 :: "r"(mbar) : "memory");
}
__device__ __forceinline__ void mbar_wait_acq(unsigned mbar, unsigned ph) {
    asm volatile(
        "{\n\t.reg .pred P;\n"
        "W0_%=:\n\t"
        "mbarrier.try_wait.parity.acquire.cluster.shared::cta.b64 P, [%0], %1, 0x989680;\n\t"
        "@P bra.uni W1_%=;\n\t"
        "bra.uni W0_%=;\n"
        "W1_%=:\n\t}"
        :: "r"(mbar), "r"(ph) : "memory");
}

// ===========================================================================
// K1: xin[s][b][i] = dot(emb[X[b,s]], W_ih[i]) + b_ih[i] + b_hh[i]
// GEMM M=32768 (m = s*64+b), N=512, K=256. Tile 64x128, double-buffered.
// ===========================================================================
__global__ void __launch_bounds__(256) k1_xin(
    const int* __restrict__ X, const float* __restrict__ emb,
    const float* __restrict__ W_ih, const float* __restrict__ b_ih,
    const float* __restrict__ b_hh)
{
    __shared__ int rsh[64];
    __shared__ __align__(16) float As[2][16 * 64];   // [buf][k][m]
    __shared__ __align__(16) float Bs[2][16 * 128];  // [buf][k][n]
    const int t  = threadIdx.x;
    const int mt = blockIdx.x;            // == s
    const int n0 = blockIdx.y * 128;
    if (t < 64) rsh[t] = X[(size_t)t * SEQ + mt];

    const int tx = t & 31, ty = t >> 5;
    const int ml = t >> 2, kq = (t & 3) * 4;
    const int vb = t >> 1, k8 = (t & 1) * 8;

    ull acc2[4][4];
#pragma unroll
    for (int rp = 0; rp < 4; rp++)
#pragma unroll
        for (int c = 0; c < 4; c++) acc2[rp][c] = 0ull;

    __syncthreads();
    const int arow = rsh[ml];
    const float* aptr = &emb[(size_t)arow * EMB + kq];
    const float* bptr = &W_ih[(size_t)(n0 + vb) * EMB + k8];

    float4 av  = *(const float4*)&aptr[0];
    float4 bv0 = *(const float4*)&bptr[0];
    float4 bv1 = *(const float4*)&bptr[4];

    for (int it = 0; it < 16; it++) {
        const int buf = it & 1;
        As[buf][(kq + 0) * 64 + ml] = av.x;
        As[buf][(kq + 1) * 64 + ml] = av.y;
        As[buf][(kq + 2) * 64 + ml] = av.z;
        As[buf][(kq + 3) * 64 + ml] = av.w;
        Bs[buf][(k8 + 0) * 128 + vb] = bv0.x;
        Bs[buf][(k8 + 1) * 128 + vb] = bv0.y;
        Bs[buf][(k8 + 2) * 128 + vb] = bv0.z;
        Bs[buf][(k8 + 3) * 128 + vb] = bv0.w;
        Bs[buf][(k8 + 4) * 128 + vb] = bv1.x;
        Bs[buf][(k8 + 5) * 128 + vb] = bv1.y;
        Bs[buf][(k8 + 6) * 128 + vb] = bv1.z;
        Bs[buf][(k8 + 7) * 128 + vb] = bv1.w;
        __syncthreads();
        if (it < 15) {
            const int k0 = (it + 1) * 16;
            av  = *(const float4*)&aptr[k0];
            bv0 = *(const float4*)&bptr[k0];
            bv1 = *(const float4*)&bptr[k0 + 4];
        }
#pragma unroll
        for (int kk = 0; kk < 16; kk++) {
            const ull* ap = (const ull*)&As[buf][kk * 64 + ty * 8];
            ull a0 = ap[0], a1 = ap[1], a2 = ap[2], a3 = ap[3];
            float4 Wv = *(const float4*)&Bs[buf][kk * 128 + tx * 4];
            ull wd[4] = {dup2(Wv.x), dup2(Wv.y), dup2(Wv.z), dup2(Wv.w)};
#pragma unroll
            for (int c = 0; c < 4; c++) {
                fma2(acc2[0][c], a0, wd[c]);
                fma2(acc2[1][c], a1, wd[c]);
                fma2(acc2[2][c], a2, wd[c]);
                fma2(acc2[3][c], a3, wd[c]);
            }
        }
    }

    const int nbase = n0 + tx * 4;
    float bias[4];
#pragma unroll
    for (int c = 0; c < 4; c++) bias[c] = b_ih[nbase + c] + b_hh[nbase + c];
#pragma unroll
    for (int rp = 0; rp < 4; rp++) {
        float2 p0 = unpack2(acc2[rp][0]);
        float2 p1 = unpack2(acc2[rp][1]);
        float2 p2 = unpack2(acc2[rp][2]);
        float2 p3 = unpack2(acc2[rp][3]);
        int bl0 = ty * 8 + 2 * rp;
        float4 o0, o1;
        o0.x = p0.x + bias[0]; o0.y = p1.x + bias[1];
        o0.z = p2.x + bias[2]; o0.w = p3.x + bias[3];
        o1.x = p0.y + bias[0]; o1.y = p1.y + bias[1];
        o1.z = p2.y + bias[2]; o1.w = p3.y + bias[3];
        *(float4*)&g_xin[((size_t)mt * BATCH + bl0) * HID + nbase]     = o0;
        *(float4*)&g_xin[((size_t)mt * BATCH + bl0 + 1) * HID + nbase] = o1;
    }
}

// ===========================================================================
// K2: persistent clustered RNN. 16 clusters x 8 CTAs, 512 threads.
// W_hh in registers. h exchange: plain st.shared::cluster to all 8 peers'
// parity buffers, signaled by count-8 mbarriers (full[2], parity-phased).
// No aligned cluster barrier in the loop. xin prefetched one step ahead.
// ===========================================================================
struct K2S {
    float hbuf[2 * 4 * 512];   // [parity][b][j]   16384 B (offset 0)
    float red[16 * 256];       //                  16384 B (offset 16384)
    ull   full[2];             //                  offset 32768
};
#define K2_FULL_OFF 32768u

__global__ void __launch_bounds__(512, 1) __cluster_dims__(8, 1, 1)
k2_rnn(const float* __restrict__ W_hh)
{
    __shared__ __align__(16) K2S sm;

    const int t = threadIdx.x;
    unsigned rank;
    asm("mov.u32 %0, %%cluster_ctarank;" : "=r"(rank));
    const int cg = blockIdx.x >> 3;
    const int b0 = cg * 4;

    const int ip   = t & 31;     // i-row base (lane)
    const int jseg = t >> 5;     // warp = 32-wide j segment (16 warps)
    const int ob   = t >> 6;     // output batch (valid for t<256)
    const int oi   = t & 63;     // output i (local)
    const int iglob = (int)rank * 64 + oi;

    // ---- W_hh rows in registers: rows (rank*64+ip, +32), j [jseg*32,+32) ----
    ull w0[16], w1[16];
    {
        const ull* wg0 = (const ull*)&W_hh[(size_t)(rank * 64 + ip) * HID + jseg * 32];
        const ull* wg1 = (const ull*)&W_hh[(size_t)(rank * 64 + ip + 32) * HID + jseg * 32];
#pragma unroll
        for (int jj = 0; jj < 16; jj++) { w0[jj] = wg0[jj]; w1[jj] = wg1[jj]; }
    }

    // ---- cluster peer addresses ----
    unsigned base = smem_u32(&sm);
    unsigned peer[8];
#pragma unroll
    for (int r = 0; r < 8; r++)
        asm("mapa.shared::cluster.u32 %0, %1, %2;"
            : "=r"(peer[r]) : "r"(base), "r"(r));
    // threads 0..7: the full-barrier of cluster CTA #t (for per-step arrive)
    unsigned arr_addr = 0;
    if (t < 8)
        asm("mapa.shared::cluster.u32 %0, %1, %2;"
            : "=r"(arr_addr) : "r"(base + K2_FULL_OFF), "r"(t));

    if (t == 0) {
        mbar_init(base + K2_FULL_OFF + 0, 8);
        mbar_init(base + K2_FULL_OFF + 8, 8);
    }
    __syncthreads();
    // all CTAs' mbarriers initialized before any remote arrive
    asm volatile("barrier.cluster.arrive.aligned;" ::: "memory");
    asm volatile("barrier.cluster.wait.aligned;" ::: "memory");

    float xv = 0.f;
    if (t < 256)
        xv = __ldg(&g_xin[((size_t)0 * BATCH + b0 + ob) * HID + iglob]);

    for (int s = 0; s < SEQ; s++) {
        // prefetch next step's xin (overlaps wait + compute)
        float xv_next = 0.f;
        if (t < 256 && s + 1 < SEQ)
            xv_next = __ldg(&g_xin[((size_t)(s + 1) * BATCH + b0 + ob) * HID + iglob]);

        float dot = 0.f;
        if (s > 0) {
            const int q = (s - 1) & 1;
            mbar_wait_acq(base + K2_FULL_OFF + (unsigned)(q * 8),
                          (unsigned)(((s - 1) >> 1) & 1));

            const float* hb = sm.hbuf + q * 2048;
            ull acc[8];
#pragma unroll
            for (int z = 0; z < 8; z++) acc[z] = 0ull;
#pragma unroll
            for (int z = 0; z < 8; z++) {
#pragma unroll
                for (int b = 0; b < 4; b++) {
                    ulonglong2 h2 =
                        *(const ulonglong2*)&hb[b * 512 + jseg * 32 + z * 4];
                    fma2(acc[b],     w0[2 * z],     h2.x);
                    fma2(acc[4 + b], w1[2 * z],     h2.x);
                    fma2(acc[b],     w0[2 * z + 1], h2.y);
                    fma2(acc[4 + b], w1[2 * z + 1], h2.y);
                }
            }
#pragma unroll
            for (int b = 0; b < 4; b++) {
                float2 pa = unpack2(acc[b]);
                float2 pb = unpack2(acc[4 + b]);
                sm.red[jseg * 256 + b * 64 + ip]      = pa.x + pa.y;
                sm.red[jseg * 256 + b * 64 + ip + 32] = pb.x + pb.y;
            }
            __syncthreads();
            if (t < 256) {
                float d0 = 0.f, d1 = 0.f;
#pragma unroll
                for (int z = 0; z < 8; z++) {
                    d0 += sm.red[(2 * z) * 256 + t];
                    d1 += sm.red[(2 * z + 1) * 256 + t];
                }
                dot = d0 + d1;
            }
        }

        float h = 0.f;
        if (t < 256) {
            h = ftanh(xv + dot);
            if (s < SEQ - 1) {
                unsigned boff = (unsigned)(((s & 1) * 2048 + ob * 512 + iglob) * 4);
#pragma unroll
                for (int r = 0; r < 8; r++)
                    asm volatile("st.shared::cluster.f32 [%0], %1;"
                                 :: "r"(peer[r] + boff), "f"(h) : "memory");
            }
        }
        __syncthreads();   // all pushes done before the release-arrives
        if (s < SEQ - 1 && t < 8)
            mbar_arrive_remote(arr_addr + (unsigned)((s & 1) * 8));

        if (t < 256)
            g_states[((size_t)s * BATCH + b0 + ob) * HID + iglob] = h;
        xv = xv_next;
    }

    // keep smem alive until all peers are done with it
    asm volatile("barrier.cluster.arrive.aligned;" ::: "memory");
    asm volatile("barrier.cluster.wait.aligned;" ::: "memory");
}

// ===========================================================================
// K3: attention + feat. One CTA per batch b, 512 threads.
// ===========================================================================
__global__ void __launch_bounds__(512) k3_attn()
{
    __shared__ float lsh[512];
    __shared__ float ash[512];
    __shared__ float red[16];
    const int b = blockIdx.x;
    const int t = threadIdx.x;
    const int lane = t & 31, wid = t >> 5;

    lsh[t] = g_states[((size_t)(SEQ - 1) * BATCH + b) * HID + t];
    __syncthreads();

    for (int s = wid; s < SEQ - 1; s += 16) {
        const float* hs = &g_states[((size_t)s * BATCH + b) * HID];
        float p = 0.f;
#pragma unroll
        for (int m = 0; m < 16; m++)
            p = fmaf(hs[lane + 32 * m], lsh[lane + 32 * m], p);
#pragma unroll
        for (int o = 16; o > 0; o >>= 1) p += __shfl_down_sync(0xffffffffu, p, o);
        if (lane == 0) ash[s] = p;
    }
    __syncthreads();

    float v = (t < SEQ - 1) ? ash[t] : -3.0e38f;
    float mx = v;
#pragma unroll
    for (int o = 16; o > 0; o >>= 1) mx = fmaxf(mx, __shfl_xor_sync(0xffffffffu, mx, o));
    if (lane == 0) red[wid] = mx;
    __syncthreads();
    float m2 = red[0];
#pragma unroll
    for (int i = 1; i < 16; i++) m2 = fmaxf(m2, red[i]);
    __syncthreads();

    float e = (t < SEQ - 1) ? __expf(v - m2) : 0.f;
    float sm = e;
#pragma unroll
    for (int o = 16; o > 0; o >>= 1) sm += __shfl_xor_sync(0xffffffffu, sm, o);
    if (lane == 0) red[wid] = sm;
    __syncthreads();
    float tot = 0.f;
#pragma unroll
    for (int i = 0; i < 16; i++) tot += red[i];
    float inv = 1.f / tot;
    __syncthreads();
    if (t < SEQ - 1) ash[t] = e * inv;
    __syncthreads();

    float ctx = 0.f;
#pragma unroll 4
    for (int s = 0; s < SEQ - 1; s++)
        ctx = fmaf(ash[s], g_states[((size_t)s * BATCH + b) * HID + t], ctx);

    g_feat[b * 1024 + t]       = ctx;
    g_feat[b * 1024 + 512 + t] = lsh[t];
}

// ===========================================================================
// K4: out[b][v] = dot(feat[b], W[v]) + bias[v]. M=64, N=32000, K=1024.
// Tile 64x128, double-buffered, one sync per k-tile. grid = 250.
// ===========================================================================
__global__ void __launch_bounds__(256) k4_out(
    const float* __restrict__ W, const float* __restrict__ bias,
    float* __restrict__ out)
{
    __shared__ __align__(16) float As[2][16 * 64];
    __shared__ __align__(16) float Bs[2][16 * 128];
    const int t  = threadIdx.x;
    const int n0 = blockIdx.x * 128;
    const int tx = t & 31, ty = t >> 5;
    const int ml = t >> 2, kq = (t & 3) * 4;
    const int vb = t >> 1, k8 = (t & 1) * 8;

    ull acc2[4][4];
#pragma unroll
    for (int rp = 0; rp < 4; rp++)
#pragma unroll
        for (int c = 0; c < 4; c++) acc2[rp][c] = 0ull;

    const float* aptr = &g_feat[(size_t)ml * 1024 + kq];
    const float* bptr = &W[(size_t)(n0 + vb) * 1024 + k8];

    float4 av  = *(const float4*)&aptr[0];
    float4 bv0 = *(const float4*)&bptr[0];
    float4 bv1 = *(const float4*)&bptr[4];

    for (int it = 0; it < 64; it++) {
        const int buf = it & 1;
        As[buf][(kq + 0) * 64 + ml] = av.x;
        As[buf][(kq + 1) * 64 + ml] = av.y;
        As[buf][(kq + 2) * 64 + ml] = av.z;
        As[buf][(kq + 3) * 64 + ml] = av.w;
        Bs[buf][(k8 + 0) * 128 + vb] = bv0.x;
        Bs[buf][(k8 + 1) * 128 + vb] = bv0.y;
        Bs[buf][(k8 + 2) * 128 + vb] = bv0.z;
        Bs[buf][(k8 + 3) * 128 + vb] = bv0.w;
        Bs[buf][(k8 + 4) * 128 + vb] = bv1.x;
        Bs[buf][(k8 + 5) * 128 + vb] = bv1.y;
        Bs[buf][(k8 + 6) * 128 + vb] = bv1.z;
        Bs[buf][(k8 + 7) * 128 + vb] = bv1.w;
        __syncthreads();
        if (it < 63) {
            const int k0 = (it + 1) * 16;
            av  = *(const float4*)&aptr[k0];
            bv0 = *(const float4*)&bptr[k0];
            bv1 = *(const float4*)&bptr[k0 + 4];
        }
#pragma unroll
        for (int kk = 0; kk < 16; kk++) {
            const ull* ap = (const ull*)&As[buf][kk * 64 + ty * 8];
            ull a0 = ap[0], a1 = ap[1], a2 = ap[2], a3 = ap[3];
            float4 Wv = *(const float4*)&Bs[buf][kk * 128 + tx * 4];
            ull wd[4] = {dup2(Wv.x), dup2(Wv.y), dup2(Wv.z), dup2(Wv.w)};
#pragma unroll
            for (int c = 0; c < 4; c++) {
                fma2(acc2[0][c], a0, wd[c]);
                fma2(acc2[1][c], a1, wd[c]);
                fma2(acc2[2][c], a2, wd[c]);
                fma2(acc2[3][c], a3, wd[c]);
            }
        }
    }

    const int nbase = n0 + tx * 4;
    float bv_0 = bias[nbase + 0], bv_1 = bias[nbase + 1];
    float bv_2 = bias[nbase + 2], bv_3 = bias[nbase + 3];
#pragma unroll
    for (int rp = 0; rp < 4; rp++) {
        float2 p0 = unpack2(acc2[rp][0]);
        float2 p1 = unpack2(acc2[rp][1]);
        float2 p2 = unpack2(acc2[rp][2]);
        float2 p3 = unpack2(acc2[rp][3]);
        int bb0 = ty * 8 + 2 * rp;
        float4 o0, o1;
        o0.x = p0.x + bv_0; o0.y = p1.x + bv_1; o0.z = p2.x + bv_2; o0.w = p3.x + bv_3;
        o1.x = p0.y + bv_0; o1.y = p1.y + bv_1; o1.z = p2.y + bv_2; o1.w = p3.y + bv_3;
        *(float4*)&out[(size_t)bb0 * VOCAB + nbase]       = o0;
        *(float4*)&out[(size_t)(bb0 + 1) * VOCAB + nbase] = o1;
    }
}

// ===========================================================================
extern "C" void kernel_launch(void* const* d_in, const int* in_sizes, int n_in,
                              void* d_out, int out_size) {
    (void)in_sizes; (void)n_in; (void)out_size;
    const int*   X    = (const int*)d_in[0];
    const float* emb  = (const float*)d_in[1];
    const float* W_ih = (const float*)d_in[2];
    const float* W_hh = (const float*)d_in[3];
    const float* b_ih = (const float*)d_in[4];
    const float* b_hh = (const float*)d_in[5];
    const float* W    = (const float*)d_in[6];
    const float* bias = (const float*)d_in[7];
    float* out = (float*)d_out;

    k1_xin<<<dim3(SEQ, 4), 256>>>(X, emb, W_ih, b_ih, b_hh);
    k2_rnn<<<128, 512>>>(W_hh);
    k3_attn<<<BATCH, 512>>>();
    k4_out<<<VOCAB / 128, 256>>>(W, bias, out);
}

// round 11
// speedup vs baseline: 1.0548x; 1.0548x over previous
#include <cuda_runtime.h>
#include <cuda_bf16.h>

#define VOCAB 32000
#define EMB   256
#define HID   512
#define BATCH 64
#define SEQ   512

typedef unsigned long long ull;

// ------------------------- device scratch (no runtime alloc) ---------------
__device__ float g_xin[(size_t)SEQ * BATCH * HID];     // [s][b][i]
__device__ float g_states[(size_t)SEQ * BATCH * HID];  // [s][b][i]
__device__ float g_feat[BATCH * 2 * HID];              // [b][1024]

// ------------------------- packed fp32x2 helpers ---------------------------
__device__ __forceinline__ void fma2(ull& d, ull a, ull b) {
    asm("fma.rn.f32x2 %0, %1, %2, %0;" : "+l"(d) : "l"(a), "l"(b));
}
__device__ __forceinline__ float2 unpack2(ull v) {
    float lo, hi;
    asm("mov.b64 {%0, %1}, %2;" : "=f"(lo), "=f"(hi) : "l"(v));
    return make_float2(lo, hi);
}
__device__ __forceinline__ ull dup2(float x) {
    ull r;
    asm("mov.b64 %0, {%1, %1};" : "=l"(r) : "f"(x));
    return r;
}
__device__ __forceinline__ unsigned smem_u32(const void* p) {
    unsigned a;
    asm("{ .reg .u64 t; cvta.to.shared.u64 t, %1; cvt.u32.u64 %0, t; }"
        : "=r"(a) : "l"(p));
    return a;
}
// fast tanh: 1 - 2/(exp(2x)+1). MUFU-based, abs err ~1e-6, exact saturation.
__device__ __forceinline__ float ftanh(float x) {
    float e = __expf(2.f * x);
    return 1.f - __fdividef(2.f, e + 1.f);
}

// ===========================================================================
// K1: xin[s][b][i] = dot(emb[X[b,s]], W_ih[i]) + b_ih[i] + b_hh[i]
// GEMM M=32768 (m = s*64+b), N=512, K=256. Tile 64x128, double-buffered.
// ===========================================================================
__global__ void __launch_bounds__(256) k1_xin(
    const int* __restrict__ X, const float* __restrict__ emb,
    const float* __restrict__ W_ih, const float* __restrict__ b_ih,
    const float* __restrict__ b_hh)
{
    __shared__ int rsh[64];
    __shared__ __align__(16) float As[2][16 * 64];   // [buf][k][m]
    __shared__ __align__(16) float Bs[2][16 * 128];  // [buf][k][n]
    const int t  = threadIdx.x;
    const int mt = blockIdx.x;            // == s
    const int n0 = blockIdx.y * 128;
    if (t < 64) rsh[t] = X[(size_t)t * SEQ + mt];

    const int tx = t & 31, ty = t >> 5;
    const int ml = t >> 2, kq = (t & 3) * 4;
    const int vb = t >> 1, k8 = (t & 1) * 8;

    ull acc2[4][4];
#pragma unroll
    for (int rp = 0; rp < 4; rp++)
#pragma unroll
        for (int c = 0; c < 4; c++) acc2[rp][c] = 0ull;

    __syncthreads();
    const int arow = rsh[ml];
    const float* aptr = &emb[(size_t)arow * EMB + kq];
    const float* bptr = &W_ih[(size_t)(n0 + vb) * EMB + k8];

    float4 av  = *(const float4*)&aptr[0];
    float4 bv0 = *(const float4*)&bptr[0];
    float4 bv1 = *(const float4*)&bptr[4];

    for (int it = 0; it < 16; it++) {
        const int buf = it & 1;
        As[buf][(kq + 0) * 64 + ml] = av.x;
        As[buf][(kq + 1) * 64 + ml] = av.y;
        As[buf][(kq + 2) * 64 + ml] = av.z;
        As[buf][(kq + 3) * 64 + ml] = av.w;
        Bs[buf][(k8 + 0) * 128 + vb] = bv0.x;
        Bs[buf][(k8 + 1) * 128 + vb] = bv0.y;
        Bs[buf][(k8 + 2) * 128 + vb] = bv0.z;
        Bs[buf][(k8 + 3) * 128 + vb] = bv0.w;
        Bs[buf][(k8 + 4) * 128 + vb] = bv1.x;
        Bs[buf][(k8 + 5) * 128 + vb] = bv1.y;
        Bs[buf][(k8 + 6) * 128 + vb] = bv1.z;
        Bs[buf][(k8 + 7) * 128 + vb] = bv1.w;
        __syncthreads();
        if (it < 15) {
            const int k0 = (it + 1) * 16;
            av  = *(const float4*)&aptr[k0];
            bv0 = *(const float4*)&bptr[k0];
            bv1 = *(const float4*)&bptr[k0 + 4];
        }
#pragma unroll
        for (int kk = 0; kk < 16; kk++) {
            const ull* ap = (const ull*)&As[buf][kk * 64 + ty * 8];
            ull a0 = ap[0], a1 = ap[1], a2 = ap[2], a3 = ap[3];
            float4 Wv = *(const float4*)&Bs[buf][kk * 128 + tx * 4];
            ull wd[4] = {dup2(Wv.x), dup2(Wv.y), dup2(Wv.z), dup2(Wv.w)};
#pragma unroll
            for (int c = 0; c < 4; c++) {
                fma2(acc2[0][c], a0, wd[c]);
                fma2(acc2[1][c], a1, wd[c]);
                fma2(acc2[2][c], a2, wd[c]);
                fma2(acc2[3][c], a3, wd[c]);
            }
        }
    }

    const int nbase = n0 + tx * 4;
    float bias[4];
#pragma unroll
    for (int c = 0; c < 4; c++) bias[c] = b_ih[nbase + c] + b_hh[nbase + c];
#pragma unroll
    for (int rp = 0; rp < 4; rp++) {
        float2 p0 = unpack2(acc2[rp][0]);
        float2 p1 = unpack2(acc2[rp][1]);
        float2 p2 = unpack2(acc2[rp][2]);
        float2 p3 = unpack2(acc2[rp][3]);
        int bl0 = ty * 8 + 2 * rp;
        float4 o0, o1;
        o0.x = p0.x + bias[0]; o0.y = p1.x + bias[1];
        o0.z = p2.x + bias[2]; o0.w = p3.x + bias[3];
        o1.x = p0.y + bias[0]; o1.y = p1.y + bias[1];
        o1.z = p2.y + bias[2]; o1.w = p3.y + bias[3];
        *(float4*)&g_xin[((size_t)mt * BATCH + bl0) * HID + nbase]     = o0;
        *(float4*)&g_xin[((size_t)mt * BATCH + bl0 + 1) * HID + nbase] = o1;
    }
}

// ===========================================================================
// K2: persistent clustered RNN (R9 proven design + ftanh + xin prefetch).
// 16 clusters x 8 CTAs, 512 threads. W_hh in registers. h exchange: plain
// st.shared::cluster to all 8 peers' parity buffers + ONE aligned cluster
// barrier per step.
// ===========================================================================
__global__ void __launch_bounds__(512, 1) __cluster_dims__(8, 1, 1)
k2_rnn(const float* __restrict__ W_hh)
{
    __shared__ __align__(16) float hbuf[2 * 4 * 512];  // [parity][b][j]
    __shared__ float red[16 * 256];                    // [jseg][b*64+i]

    const int t = threadIdx.x;
    unsigned rank;
    asm("mov.u32 %0, %%cluster_ctarank;" : "=r"(rank));
    const int cg = blockIdx.x >> 3;
    const int b0 = cg * 4;

    const int ip   = t & 31;     // i-row base (lane)
    const int jseg = t >> 5;     // warp = 32-wide j segment (16 warps)
    const int ob   = t >> 6;     // output batch (valid for t<256)
    const int oi   = t & 63;     // output i (local)
    const int iglob = (int)rank * 64 + oi;

    // ---- W_hh rows in registers: rows (rank*64+ip, +32), j [jseg*32,+32) ----
    ull w0[16], w1[16];
    {
        const ull* wg0 = (const ull*)&W_hh[(size_t)(rank * 64 + ip) * HID + jseg * 32];
        const ull* wg1 = (const ull*)&W_hh[(size_t)(rank * 64 + ip + 32) * HID + jseg * 32];
#pragma unroll
        for (int jj = 0; jj < 16; jj++) { w0[jj] = wg0[jj]; w1[jj] = wg1[jj]; }
    }

    // peer base addresses of hbuf (DSMEM)
    unsigned hb32 = smem_u32(hbuf);
    unsigned peer[8];
#pragma unroll
    for (int r = 0; r < 8; r++)
        asm("mapa.shared::cluster.u32 %0, %1, %2;"
            : "=r"(peer[r]) : "r"(hb32), "r"(r));

    // all cluster smem live before first DSMEM push
    asm volatile("barrier.cluster.arrive.aligned;" ::: "memory");
    asm volatile("barrier.cluster.wait.aligned;" ::: "memory");

    float xv = 0.f;
    if (t < 256)
        xv = __ldg(&g_xin[((size_t)0 * BATCH + b0 + ob) * HID + iglob]);

    for (int s = 0; s < SEQ; s++) {
        // prefetch next step's xin (hidden behind compute)
        float xv_next = 0.f;
        if (t < 256 && s + 1 < SEQ)
            xv_next = __ldg(&g_xin[((size_t)(s + 1) * BATCH + b0 + ob) * HID + iglob]);

        float dot = 0.f;
        if (s > 0) {
            const float* hb = hbuf + ((s - 1) & 1) * 2048;
            ull acc[8];
#pragma unroll
            for (int z = 0; z < 8; z++) acc[z] = 0ull;
#pragma unroll
            for (int z = 0; z < 8; z++) {
#pragma unroll
                for (int b = 0; b < 4; b++) {
                    // broadcast LDS.128: h[b][jseg*32 + 4z .. +3]
                    ulonglong2 h2 =
                        *(const ulonglong2*)&hb[b * 512 + jseg * 32 + z * 4];
                    fma2(acc[b],     w0[2 * z],     h2.x);
                    fma2(acc[4 + b], w1[2 * z],     h2.x);
                    fma2(acc[b],     w0[2 * z + 1], h2.y);
                    fma2(acc[4 + b], w1[2 * z + 1], h2.y);
                }
            }
#pragma unroll
            for (int b = 0; b < 4; b++) {
                float2 pa = unpack2(acc[b]);
                float2 pb = unpack2(acc[4 + b]);
                red[jseg * 256 + b * 64 + ip]      = pa.x + pa.y;
                red[jseg * 256 + b * 64 + ip + 32] = pb.x + pb.y;
            }
            __syncthreads();
            if (t < 256) {
                float d0 = 0.f, d1 = 0.f;
#pragma unroll
                for (int z = 0; z < 8; z++) {
                    d0 += red[(2 * z) * 256 + t];
                    d1 += red[(2 * z + 1) * 256 + t];
                }
                dot = d0 + d1;
            }
        }

        if (t < 256) {
            float h = ftanh(xv + dot);
            if (s < SEQ - 1) {
                unsigned boff = (unsigned)(((s & 1) * 2048 + ob * 512 + iglob) * 4);
#pragma unroll
                for (int r = 0; r < 8; r++)
                    asm volatile("st.shared::cluster.f32 [%0], %1;"
                                 :: "r"(peer[r] + boff), "f"(h) : "memory");
            }
            asm volatile("barrier.cluster.arrive.aligned;" ::: "memory");
            g_states[((size_t)s * BATCH + b0 + ob) * HID + iglob] = h;
        } else {
            asm volatile("barrier.cluster.arrive.aligned;" ::: "memory");
        }
        asm volatile("barrier.cluster.wait.aligned;" ::: "memory");
        xv = xv_next;
    }
}

// ===========================================================================
// K3: attention + feat. One CTA per batch b, 512 threads.
// ===========================================================================
__global__ void __launch_bounds__(512) k3_attn()
{
    __shared__ float lsh[512];
    __shared__ float ash[512];
    __shared__ float red[16];
    const int b = blockIdx.x;
    const int t = threadIdx.x;
    const int lane = t & 31, wid = t >> 5;

    lsh[t] = g_states[((size_t)(SEQ - 1) * BATCH + b) * HID + t];
    __syncthreads();

    for (int s = wid; s < SEQ - 1; s += 16) {
        const float* hs = &g_states[((size_t)s * BATCH + b) * HID];
        float p = 0.f;
#pragma unroll
        for (int m = 0; m < 16; m++)
            p = fmaf(hs[lane + 32 * m], lsh[lane + 32 * m], p);
#pragma unroll
        for (int o = 16; o > 0; o >>= 1) p += __shfl_down_sync(0xffffffffu, p, o);
        if (lane == 0) ash[s] = p;
    }
    __syncthreads();

    float v = (t < SEQ - 1) ? ash[t] : -3.0e38f;
    float mx = v;
#pragma unroll
    for (int o = 16; o > 0; o >>= 1) mx = fmaxf(mx, __shfl_xor_sync(0xffffffffu, mx, o));
    if (lane == 0) red[wid] = mx;
    __syncthreads();
    float m2 = red[0];
#pragma unroll
    for (int i = 1; i < 16; i++) m2 = fmaxf(m2, red[i]);
    __syncthreads();

    float e = (t < SEQ - 1) ? __expf(v - m2) : 0.f;
    float sm = e;
#pragma unroll
    for (int o = 16; o > 0; o >>= 1) sm += __shfl_xor_sync(0xffffffffu, sm, o);
    if (lane == 0) red[wid] = sm;
    __syncthreads();
    float tot = 0.f;
#pragma unroll
    for (int i = 0; i < 16; i++) tot += red[i];
    float inv = 1.f / tot;
    __syncthreads();
    if (t < SEQ - 1) ash[t] = e * inv;
    __syncthreads();

    float ctx = 0.f;
#pragma unroll 4
    for (int s = 0; s < SEQ - 1; s++)
        ctx = fmaf(ash[s], g_states[((size_t)s * BATCH + b) * HID + t], ctx);

    g_feat[b * 1024 + t]       = ctx;
    g_feat[b * 1024 + 512 + t] = lsh[t];
}

// ===========================================================================
// K4: out[b][v] = dot(feat[b], W[v]) + bias[v]. M=64, N=32000, K=1024.
// Tile 64x256, grid = 125 -> ONE full wave on 148 SMs. 8m x 8n per thread.
// Double-buffered smem (40 KB static), coalesced row-per-thread B fill.
// ===========================================================================
__global__ void __launch_bounds__(256) k4_out(
    const float* __restrict__ W, const float* __restrict__ bias,
    float* __restrict__ out)
{
    __shared__ __align__(16) float As[2][16 * 64];    // 8 KB
    __shared__ __align__(16) float Bs[2][16 * 256];   // 32 KB
    const int t  = threadIdx.x;
    const int n0 = blockIdx.x * 256;
    const int tx = t & 31, ty = t >> 5;
    const int ml = t >> 2, kq = (t & 3) * 4;

    ull acc2[4][8];   // [row-pair][n]; n 0..3 -> tx*4+c, n 4..7 -> 128+tx*4+c
#pragma unroll
    for (int rp = 0; rp < 4; rp++)
#pragma unroll
        for (int c = 0; c < 8; c++) acc2[rp][c] = 0ull;

    const float* aptr = &g_feat[(size_t)ml * 1024 + kq];
    const float* bptr = &W[(size_t)(n0 + t) * 1024];   // this thread's n-row

    float4 av = *(const float4*)&aptr[0];
    float4 bq0 = *(const float4*)&bptr[0];
    float4 bq1 = *(const float4*)&bptr[4];
    float4 bq2 = *(const float4*)&bptr[8];
    float4 bq3 = *(const float4*)&bptr[12];

    for (int it = 0; it < 64; it++) {
        const int buf = it & 1;
        As[buf][(kq + 0) * 64 + ml] = av.x;
        As[buf][(kq + 1) * 64 + ml] = av.y;
        As[buf][(kq + 2) * 64 + ml] = av.z;
        As[buf][(kq + 3) * 64 + ml] = av.w;
        Bs[buf][ 0 * 256 + t] = bq0.x;
        Bs[buf][ 1 * 256 + t] = bq0.y;
        Bs[buf][ 2 * 256 + t] = bq0.z;
        Bs[buf][ 3 * 256 + t] = bq0.w;
        Bs[buf][ 4 * 256 + t] = bq1.x;
        Bs[buf][ 5 * 256 + t] = bq1.y;
        Bs[buf][ 6 * 256 + t] = bq1.z;
        Bs[buf][ 7 * 256 + t] = bq1.w;
        Bs[buf][ 8 * 256 + t] = bq2.x;
        Bs[buf][ 9 * 256 + t] = bq2.y;
        Bs[buf][10 * 256 + t] = bq2.z;
        Bs[buf][11 * 256 + t] = bq2.w;
        Bs[buf][12 * 256 + t] = bq3.x;
        Bs[buf][13 * 256 + t] = bq3.y;
        Bs[buf][14 * 256 + t] = bq3.z;
        Bs[buf][15 * 256 + t] = bq3.w;
        __syncthreads();
        if (it < 63) {
            const int k0 = (it + 1) * 16;
            av  = *(const float4*)&aptr[k0];
            bq0 = *(const float4*)&bptr[k0];
            bq1 = *(const float4*)&bptr[k0 + 4];
            bq2 = *(const float4*)&bptr[k0 + 8];
            bq3 = *(const float4*)&bptr[k0 + 12];
        }
#pragma unroll
        for (int kk = 0; kk < 16; kk++) {
            const ull* ap = (const ull*)&As[buf][kk * 64 + ty * 8];
            ull a0 = ap[0], a1 = ap[1], a2 = ap[2], a3 = ap[3];
            float4 Wv0 = *(const float4*)&Bs[buf][kk * 256 + tx * 4];
            float4 Wv1 = *(const float4*)&Bs[buf][kk * 256 + 128 + tx * 4];
            ull wd[8] = {dup2(Wv0.x), dup2(Wv0.y), dup2(Wv0.z), dup2(Wv0.w),
                         dup2(Wv1.x), dup2(Wv1.y), dup2(Wv1.z), dup2(Wv1.w)};
#pragma unroll
            for (int c = 0; c < 8; c++) {
                fma2(acc2[0][c], a0, wd[c]);
                fma2(acc2[1][c], a1, wd[c]);
                fma2(acc2[2][c], a2, wd[c]);
                fma2(acc2[3][c], a3, wd[c]);
            }
        }
        __syncthreads();
    }

    const int nb0 = n0 + tx * 4;
    const int nb1 = nb0 + 128;
    float bv[8];
#pragma unroll
    for (int c = 0; c < 4; c++) { bv[c] = bias[nb0 + c]; bv[4 + c] = bias[nb1 + c]; }
#pragma unroll
    for (int rp = 0; rp < 4; rp++) {
        float2 p[8];
#pragma unroll
        for (int c = 0; c < 8; c++) p[c] = unpack2(acc2[rp][c]);
        int bb0 = ty * 8 + 2 * rp;
        float4 o0, o1, o2, o3;
        o0.x = p[0].x + bv[0]; o0.y = p[1].x + bv[1];
        o0.z = p[2].x + bv[2]; o0.w = p[3].x + bv[3];
        o1.x = p[0].y + bv[0]; o1.y = p[1].y + bv[1];
        o1.z = p[2].y + bv[2]; o1.w = p[3].y + bv[3];
        o2.x = p[4].x + bv[4]; o2.y = p[5].x + bv[5];
        o2.z = p[6].x + bv[6]; o2.w = p[7].x + bv[7];
        o3.x = p[4].y + bv[4]; o3.y = p[5].y + bv[5];
        o3.z = p[6].y + bv[6]; o3.w = p[7].y + bv[7];
        *(float4*)&out[(size_t)bb0 * VOCAB + nb0]       = o0;
        *(float4*)&out[(size_t)(bb0 + 1) * VOCAB + nb0] = o1;
        *(float4*)&out[(size_t)bb0 * VOCAB + nb1]       = o2;
        *(float4*)&out[(size_t)(bb0 + 1) * VOCAB + nb1] = o3;
    }
}

// ===========================================================================
extern "C" void kernel_launch(void* const* d_in, const int* in_sizes, int n_in,
                              void* d_out, int out_size) {
    (void)in_sizes; (void)n_in; (void)out_size;
    const int*   X    = (const int*)d_in[0];
    const float* emb  = (const float*)d_in[1];
    const float* W_ih = (const float*)d_in[2];
    const float* W_hh = (const float*)d_in[3];
    const float* b_ih = (const float*)d_in[4];
    const float* b_hh = (const float*)d_in[5];
    const float* W    = (const float*)d_in[6];
    const float* bias = (const float*)d_in[7];
    float* out = (float*)d_out;

    k1_xin<<<dim3(SEQ, 4), 256>>>(X, emb, W_ih, b_ih, b_hh);
    k2_rnn<<<128, 512>>>(W_hh);
    k3_attn<<<BATCH, 512>>>();
    k4_out<<<VOCAB / 256, 256>>>(W, bias, out);
}